// round 7
// baseline (speedup 1.0000x reference)
#include <cuda_runtime.h>
#include <cuda_bf16.h>

// Problem constants
#define B 8
#define N 2048
#define D 1024
#define G 8
#define CAP 320
#define NTOK (B*N)              // 16384
#define SLAB (G*CAP)            // 2560 floats per token
#define TB 32                   // tokens per gate block
#define NGATE (NTOK/TB)         // 512 gate blocks
#define NZERO 1024              // zero blocks
#define TOTAL_F4 (NTOK*SLAB/4)  // 10485760
#define ZBLK (TOTAL_F4/NZERO)   // 10240 float4 per zero block
#define ZPT (ZBLK/256)          // 40 float4 per zero thread
#define NSCAN 8                 // scan blocks (one per batch), bids 0..7

// Scratch (device globals; no allocation allowed)
__device__ float4 g_rec[NTOK];      // {pack bits, g1n, g2n, 0}
__device__ int    g_ctr_gate;       // zero-initialized; reset at end of launch
__device__ int    g_ctr_zero;
__device__ int    g_ctr_scan;

// ---------------------------------------------------------------------------
// Single fused kernel, 1544 blocks x 256 threads:
//   bid 0..7                  -> scan+scatter block for batch bid
//   bid>=8, (bid-8)%3 == 0    -> gate block   (512)
//   bid>=8, otherwise         -> zero block   (1024)
// Scan blocks spin-wait on counters: scan compute overlaps the zero-store
// drain; the scatter is ordered after ALL zero stores via the zero counter.
// ---------------------------------------------------------------------------
__global__ __launch_bounds__(256) void k_all(const float* __restrict__ x,
                                             const float* __restrict__ w,
                                             float* __restrict__ out) {
    int bid = blockIdx.x;
    int tid = threadIdx.x;
    const unsigned FULL = 0xffffffffu;

    if (bid >= NSCAN) {
        int m = bid - NSCAN;
        int mod = m % 3;

        if (mod != 0) {
            // ---------------- zero role ----------------
            int zid = (m / 3) * 2 + (mod - 1);          // 0..1023
            float4* zbase = (float4*)out + (size_t)zid * ZBLK + tid;
            const float4 ZV = make_float4(0.f, 0.f, 0.f, 0.f);
#pragma unroll
            for (int j = 0; j < ZPT; j++)
                zbase[j * 256] = ZV;
            __threadfence();            // make this thread's stores visible
            __syncthreads();            // all threads' fences done
            if (tid == 0) atomicAdd(&g_ctr_zero, 1);
            return;
        }

        // ---------------- gate role (proven R5 kernel) ----------------
        __shared__ float part[G * 8 * TB];   // 8 KB

        int warp = tid >> 5, lane = tid & 31;
        int k0 = warp * 128 + lane * 4;

        float4 wv0 = *(const float4*)(w + k0 * G + 0);
        float4 wv1 = *(const float4*)(w + k0 * G + 4);
        float4 wv2 = *(const float4*)(w + k0 * G + 8);
        float4 wv3 = *(const float4*)(w + k0 * G + 12);
        float4 wv4 = *(const float4*)(w + k0 * G + 16);
        float4 wv5 = *(const float4*)(w + k0 * G + 20);
        float4 wv6 = *(const float4*)(w + k0 * G + 24);
        float4 wv7 = *(const float4*)(w + k0 * G + 28);
        float wreg[G][4];
        wreg[0][0]=wv0.x; wreg[1][0]=wv0.y; wreg[2][0]=wv0.z; wreg[3][0]=wv0.w;
        wreg[4][0]=wv1.x; wreg[5][0]=wv1.y; wreg[6][0]=wv1.z; wreg[7][0]=wv1.w;
        wreg[0][1]=wv2.x; wreg[1][1]=wv2.y; wreg[2][1]=wv2.z; wreg[3][1]=wv2.w;
        wreg[4][1]=wv3.x; wreg[5][1]=wv3.y; wreg[6][1]=wv3.z; wreg[7][1]=wv3.w;
        wreg[0][2]=wv4.x; wreg[1][2]=wv4.y; wreg[2][2]=wv4.z; wreg[3][2]=wv4.w;
        wreg[4][2]=wv5.x; wreg[5][2]=wv5.y; wreg[6][2]=wv5.z; wreg[7][2]=wv5.w;
        wreg[0][3]=wv6.x; wreg[1][3]=wv6.y; wreg[2][3]=wv6.z; wreg[3][3]=wv6.w;
        wreg[4][3]=wv7.x; wreg[5][3]=wv7.y; wreg[6][3]=wv7.z; wreg[7][3]=wv7.w;

        int tok0 = (m / 3) * TB;
        int bit0 = lane & 1;
        int my_e = (lane & 1) * 4 + (lane & 2) + ((lane >> 2) & 1);

#pragma unroll 4
        for (int t = 0; t < TB; t++) {
            const float4 xv = *(const float4*)(x + (size_t)(tok0 + t) * D + k0);

            float acc[G];
#pragma unroll
            for (int e = 0; e < G; e++) {
                acc[e] = fmaf(xv.x, wreg[e][0],
                         fmaf(xv.y, wreg[e][1],
                         fmaf(xv.z, wreg[e][2],
                              xv.w * wreg[e][3])));
            }

            float a0 = (bit0 ? acc[4] : acc[0]) + __shfl_xor_sync(FULL, bit0 ? acc[0] : acc[4], 1);
            float a1 = (bit0 ? acc[5] : acc[1]) + __shfl_xor_sync(FULL, bit0 ? acc[1] : acc[5], 1);
            float a2 = (bit0 ? acc[6] : acc[2]) + __shfl_xor_sync(FULL, bit0 ? acc[2] : acc[6], 1);
            float a3 = (bit0 ? acc[7] : acc[3]) + __shfl_xor_sync(FULL, bit0 ? acc[3] : acc[7], 1);
            int bit1 = (lane >> 1) & 1;
            float b0 = (bit1 ? a2 : a0) + __shfl_xor_sync(FULL, bit1 ? a0 : a2, 2);
            float b1 = (bit1 ? a3 : a1) + __shfl_xor_sync(FULL, bit1 ? a1 : a3, 2);
            int bit2 = (lane >> 2) & 1;
            float c = (bit2 ? b1 : b0) + __shfl_xor_sync(FULL, bit2 ? b0 : b1, 4);
            c += __shfl_xor_sync(FULL, c, 8);
            c += __shfl_xor_sync(FULL, c, 16);

            if (lane < 8)
                part[(my_e * 8 + warp) * TB + t] = c;
        }
        __syncthreads();

        if (tid < TB) {
            int t = tid;
            float p[G];
#pragma unroll
            for (int e = 0; e < G; e++) {
                float s = 0.f;
#pragma unroll
                for (int wq = 0; wq < 8; wq++) s += part[(e * 8 + wq) * TB + t];
                p[e] = s;
            }
            float mx = p[0];
#pragma unroll
            for (int e = 1; e < G; e++) mx = fmaxf(mx, p[e]);
            float s = 0.f;
#pragma unroll
            for (int e = 0; e < G; e++) { p[e] = expf(p[e] - mx); s += p[e]; }
            float inv = 1.f / s;
#pragma unroll
            for (int e = 0; e < G; e++) p[e] *= inv;

            int i1 = 0; float g1 = p[0];
#pragma unroll
            for (int e = 1; e < G; e++) if (p[e] > g1) { g1 = p[e]; i1 = e; }
            int i2 = 0; float g2 = -1.f;
#pragma unroll
            for (int e = 0; e < G; e++)
                if (e != i1 && p[e] > g2) { g2 = p[e]; i2 = e; }

            float g1n = g1 / (g1 + g2 + 1e-9f);
            float g2n = g2 / (g1n + g2 + 1e-9f);
            int use2 = (g2n > 0.2f) ? 1 : 0;

            int pack = i1 | (i2 << 4) | (use2 << 8);
            g_rec[tok0 + t] = make_float4(__int_as_float(pack), g1n, g2n, 0.f);
        }
        __threadfence();
        __syncthreads();
        if (tid == 0) atomicAdd(&g_ctr_gate, 1);
        return;
    }

    // ======================= scan + scatter role =======================
    // bid 0..7, one per batch. 256 threads x 8 tokens.
    __shared__ unsigned long long wlo[8], whi[8];
    __shared__ int count1[G];

    // Wait for all gate blocks
    if (tid == 0) {
        while (atomicAdd(&g_ctr_gate, 0) < NGATE) __nanosleep(128);
    }
    __syncthreads();
    __threadfence();   // acquire: g_rec reads below see gate writes

    int b = bid;
    int warp = tid >> 5, lane = tid & 31;
    int base = b * N + tid * 8;

    int pk[8]; float gg1[8], gg2[8];
#pragma unroll
    for (int j = 0; j < 8; j++) {
        float4 r = g_rec[base + j];
        pk[j] = __float_as_int(r.x);
        gg1[j] = r.y; gg2[j] = r.z;
    }

    // ---- pass 1: top-1 ----
    unsigned long long lo = 0, hi = 0;
#pragma unroll
    for (int j = 0; j < 8; j++) {
        int i1 = pk[j] & 15;
        if (i1 < 4) lo += 1ULL << (i1 * 16); else hi += 1ULL << ((i1 - 4) * 16);
    }
    unsigned long long slo = lo, shi = hi;
#pragma unroll
    for (int o = 1; o < 32; o <<= 1) {
        unsigned long long t1 = __shfl_up_sync(FULL, slo, o);
        unsigned long long t2 = __shfl_up_sync(FULL, shi, o);
        if (lane >= o) { slo += t1; shi += t2; }
    }
    if (lane == 31) { wlo[warp] = slo; whi[warp] = shi; }
    __syncthreads();
    unsigned long long plo = 0, phi = 0, tlo = 0, thi = 0;
#pragma unroll
    for (int ww = 0; ww < 8; ww++) {
        unsigned long long a = wlo[ww], c = whi[ww];
        if (ww < warp) { plo += a; phi += c; }
        tlo += a; thi += c;
    }
    unsigned long long exlo = plo + slo - lo;
    unsigned long long exhi = phi + shi - hi;
#pragma unroll
    for (int e = 0; e < 4; e++) {
        count1[e]     = min((int)((tlo >> (e * 16)) & 0xFFFF), CAP);
        count1[e + 4] = min((int)((thi >> (e * 16)) & 0xFFFF), CAP);
    }
    int pos1[8];
    {
        unsigned long long rlo = exlo, rhi = exhi;
#pragma unroll
        for (int j = 0; j < 8; j++) {
            int i1 = pk[j] & 15;
            pos1[j] = (i1 < 4) ? (int)((rlo >> (i1 * 16)) & 0xFFFF)
                               : (int)((rhi >> ((i1 - 4) * 16)) & 0xFFFF);
            if (i1 < 4) rlo += 1ULL << (i1 * 16); else rhi += 1ULL << ((i1 - 4) * 16);
        }
    }
    __syncthreads();   // wlo/whi reuse

    // ---- pass 2: top-2 ----
    lo = 0; hi = 0;
#pragma unroll
    for (int j = 0; j < 8; j++) {
        if (pk[j] >> 8) {
            int i2 = (pk[j] >> 4) & 15;
            if (i2 < 4) lo += 1ULL << (i2 * 16); else hi += 1ULL << ((i2 - 4) * 16);
        }
    }
    slo = lo; shi = hi;
#pragma unroll
    for (int o = 1; o < 32; o <<= 1) {
        unsigned long long t1 = __shfl_up_sync(FULL, slo, o);
        unsigned long long t2 = __shfl_up_sync(FULL, shi, o);
        if (lane >= o) { slo += t1; shi += t2; }
    }
    if (lane == 31) { wlo[warp] = slo; whi[warp] = shi; }
    __syncthreads();
    plo = 0; phi = 0;
#pragma unroll
    for (int ww = 0; ww < 8; ww++) {
        if (ww < warp) { plo += wlo[ww]; phi += whi[ww]; }
    }
    exlo = plo + slo - lo;
    exhi = phi + shi - hi;

    // Compute final scatter targets into registers (before zero-wait)
    int soff1[8], soff2[8];
    {
        unsigned long long rlo = exlo, rhi = exhi;
#pragma unroll
        for (int j = 0; j < 8; j++) {
            int i1 = pk[j] & 15, i2 = (pk[j] >> 4) & 15, use2 = pk[j] >> 8;
            soff1[j] = (pos1[j] < CAP) ? i1 * CAP + pos1[j] : -1;
            soff2[j] = -1;
            if (use2) {
                int p = (i2 < 4) ? (int)((rlo >> (i2 * 16)) & 0xFFFF)
                                 : (int)((rhi >> ((i2 - 4) * 16)) & 0xFFFF);
                int pos2 = count1[i2] + p;
                if (pos2 < CAP) soff2[j] = i2 * CAP + pos2;
                if (i2 < 4) rlo += 1ULL << (i2 * 16); else rhi += 1ULL << ((i2 - 4) * 16);
            }
        }
    }

    // Wait for all zero blocks (orders scatter after zero-fill)
    if (tid == 0) {
        while (atomicAdd(&g_ctr_zero, 0) < NZERO) __nanosleep(128);
    }
    __syncthreads();
    __threadfence();

    // Scatter
#pragma unroll
    for (int j = 0; j < 8; j++) {
        int t = base + j;
        float* o = out + (size_t)t * SLAB;
        if (soff1[j] >= 0) o[soff1[j]] = gg1[j];
        if (soff2[j] >= 0) o[soff2[j]] = gg2[j];
    }

    // Counter reset for graph replay: last scan block to finish resets all.
    __syncthreads();
    if (tid == 0) {
        int v = atomicAdd(&g_ctr_scan, 1);
        if (v == NSCAN - 1) {
            g_ctr_gate = 0;
            g_ctr_zero = 0;
            g_ctr_scan = 0;
            __threadfence();
        }
    }
}

extern "C" void kernel_launch(void* const* d_in, const int* in_sizes, int n_in,
                              void* d_out, int out_size) {
    const float* x = (const float*)d_in[0];
    const float* w = (const float*)d_in[1];
    float* out = (float*)d_out;

    k_all<<<NSCAN + NGATE + NZERO, 256>>>(x, w, out);
}

// round 8
// speedup vs baseline: 1.1177x; 1.1177x over previous
#include <cuda_runtime.h>
#include <cuda_bf16.h>

// Problem constants
#define B 8
#define N 2048
#define D 1024
#define G 8
#define CAP 320
#define NTOK (B*N)              // 16384
#define SLAB (G*CAP)            // 2560 floats per token
#define TB 32                   // tokens per gate block
#define NGATE (NTOK/TB)         // 512 gate blocks
#define TOTAL_F4 (NTOK*SLAB/4)  // 10485760 float4
#define ZBLK 10240              // float4 per zero chunk (= 16 token slabs)
#define NCHUNK (TOTAL_F4/ZBLK)  // 1024 chunks
#define NZ1 384                 // chunks zeroed in K1 (batches 0..2)
#define NZ2 (NCHUNK-NZ1)        // 640 chunks zeroed in K2 (batches 3..7)
#define ZPT1 (ZBLK/256)         // 40 f4/thread in K1 (256 thr)
#define ZPT2 (ZBLK/512)         // 20 f4/thread in K2 (512 thr)

// Scratch (device globals; no allocation allowed)
__device__ float4 g_rec[NTOK];      // {pack bits, g1n, g2n, 0}
__device__ int    g_ctr_zero;       // K2 zero-chunk completions
__device__ int    g_ctr_done;       // K2 scan-block completions

// ---------------------------------------------------------------------------
// K1: 896 blocks x 256 threads, mod-7 interleave (4 gate : 3 zero).
//   gate blocks (512): proven R5 gating, writes g_rec.
//   zero blocks (384): zero chunks 0..383 (output of batches 0..2).
// ---------------------------------------------------------------------------
__global__ __launch_bounds__(256) void k_gz(const float* __restrict__ x,
                                            const float* __restrict__ w,
                                            float* __restrict__ out) {
    int bid = blockIdx.x;
    int mod = bid % 7;
    int tid = threadIdx.x;
    const unsigned FULL = 0xffffffffu;

    if (mod >= 4) {
        // ---------------- zero role ----------------
        int zid = (bid / 7) * 3 + (mod - 4);          // 0..383
        float4* zbase = (float4*)out + (size_t)zid * ZBLK + tid;
        const float4 ZV = make_float4(0.f, 0.f, 0.f, 0.f);
#pragma unroll
        for (int j = 0; j < ZPT1; j++)
            zbase[j * 256] = ZV;
        return;
    }

    // ---------------- gate role ----------------
    __shared__ float part[G * 8 * TB];   // 8 KB

    int warp = tid >> 5, lane = tid & 31;
    int k0 = warp * 128 + lane * 4;

    float4 wv0 = *(const float4*)(w + k0 * G + 0);
    float4 wv1 = *(const float4*)(w + k0 * G + 4);
    float4 wv2 = *(const float4*)(w + k0 * G + 8);
    float4 wv3 = *(const float4*)(w + k0 * G + 12);
    float4 wv4 = *(const float4*)(w + k0 * G + 16);
    float4 wv5 = *(const float4*)(w + k0 * G + 20);
    float4 wv6 = *(const float4*)(w + k0 * G + 24);
    float4 wv7 = *(const float4*)(w + k0 * G + 28);
    float wreg[G][4];
    wreg[0][0]=wv0.x; wreg[1][0]=wv0.y; wreg[2][0]=wv0.z; wreg[3][0]=wv0.w;
    wreg[4][0]=wv1.x; wreg[5][0]=wv1.y; wreg[6][0]=wv1.z; wreg[7][0]=wv1.w;
    wreg[0][1]=wv2.x; wreg[1][1]=wv2.y; wreg[2][1]=wv2.z; wreg[3][1]=wv2.w;
    wreg[4][1]=wv3.x; wreg[5][1]=wv3.y; wreg[6][1]=wv3.z; wreg[7][1]=wv3.w;
    wreg[0][2]=wv4.x; wreg[1][2]=wv4.y; wreg[2][2]=wv4.z; wreg[3][2]=wv4.w;
    wreg[4][2]=wv5.x; wreg[5][2]=wv5.y; wreg[6][2]=wv5.z; wreg[7][2]=wv5.w;
    wreg[0][3]=wv6.x; wreg[1][3]=wv6.y; wreg[2][3]=wv6.z; wreg[3][3]=wv6.w;
    wreg[4][3]=wv7.x; wreg[5][3]=wv7.y; wreg[6][3]=wv7.z; wreg[7][3]=wv7.w;

    int tok0 = ((bid / 7) * 4 + mod) * TB;
    int bit0 = lane & 1;
    int my_e = (lane & 1) * 4 + (lane & 2) + ((lane >> 2) & 1);

#pragma unroll 4
    for (int t = 0; t < TB; t++) {
        const float4 xv = *(const float4*)(x + (size_t)(tok0 + t) * D + k0);

        float acc[G];
#pragma unroll
        for (int e = 0; e < G; e++) {
            acc[e] = fmaf(xv.x, wreg[e][0],
                     fmaf(xv.y, wreg[e][1],
                     fmaf(xv.z, wreg[e][2],
                          xv.w * wreg[e][3])));
        }

        float a0 = (bit0 ? acc[4] : acc[0]) + __shfl_xor_sync(FULL, bit0 ? acc[0] : acc[4], 1);
        float a1 = (bit0 ? acc[5] : acc[1]) + __shfl_xor_sync(FULL, bit0 ? acc[1] : acc[5], 1);
        float a2 = (bit0 ? acc[6] : acc[2]) + __shfl_xor_sync(FULL, bit0 ? acc[2] : acc[6], 1);
        float a3 = (bit0 ? acc[7] : acc[3]) + __shfl_xor_sync(FULL, bit0 ? acc[3] : acc[7], 1);
        int bit1 = (lane >> 1) & 1;
        float b0 = (bit1 ? a2 : a0) + __shfl_xor_sync(FULL, bit1 ? a0 : a2, 2);
        float b1 = (bit1 ? a3 : a1) + __shfl_xor_sync(FULL, bit1 ? a1 : a3, 2);
        int bit2 = (lane >> 2) & 1;
        float c = (bit2 ? b1 : b0) + __shfl_xor_sync(FULL, bit2 ? b0 : b1, 4);
        c += __shfl_xor_sync(FULL, c, 8);
        c += __shfl_xor_sync(FULL, c, 16);

        if (lane < 8)
            part[(my_e * 8 + warp) * TB + t] = c;
    }
    __syncthreads();

    if (tid < TB) {
        int t = tid;
        float p[G];
#pragma unroll
        for (int e = 0; e < G; e++) {
            float s = 0.f;
#pragma unroll
            for (int wq = 0; wq < 8; wq++) s += part[(e * 8 + wq) * TB + t];
            p[e] = s;
        }
        float m = p[0];
#pragma unroll
        for (int e = 1; e < G; e++) m = fmaxf(m, p[e]);
        float s = 0.f;
#pragma unroll
        for (int e = 0; e < G; e++) { p[e] = expf(p[e] - m); s += p[e]; }
        float inv = 1.f / s;
#pragma unroll
        for (int e = 0; e < G; e++) p[e] *= inv;

        int i1 = 0; float g1 = p[0];
#pragma unroll
        for (int e = 1; e < G; e++) if (p[e] > g1) { g1 = p[e]; i1 = e; }
        int i2 = 0; float g2 = -1.f;
#pragma unroll
        for (int e = 0; e < G; e++)
            if (e != i1 && p[e] > g2) { g2 = p[e]; i2 = e; }

        float g1n = g1 / (g1 + g2 + 1e-9f);
        float g2n = g2 / (g1n + g2 + 1e-9f);
        int use2 = (g2n > 0.2f) ? 1 : 0;

        int pack = i1 | (i2 << 4) | (use2 << 8);
        g_rec[tok0 + t] = make_float4(__int_as_float(pack), g1n, g2n, 0.f);
    }
}

// ---------------------------------------------------------------------------
// K2: 648 blocks x 512 threads.
//   bid 0..7   : scan+scatter for batch bid (R6-proven shuffle scan).
//                Batches 3..7 spin until all K2 zero chunks complete.
//   bid 8..647 : zero chunks 384..1023 (output of batches 3..7), then
//                release-count on g_ctr_zero.
// ---------------------------------------------------------------------------
__global__ __launch_bounds__(512) void k_zs(float* __restrict__ out) {
    int bid = blockIdx.x;
    int tid = threadIdx.x;
    const unsigned FULL = 0xffffffffu;

    if (bid >= 8) {
        // ---------------- zero role ----------------
        int zid = NZ1 + (bid - 8);                    // 384..1023
        float4* zbase = (float4*)out + (size_t)zid * ZBLK + tid;
        const float4 ZV = make_float4(0.f, 0.f, 0.f, 0.f);
#pragma unroll
        for (int j = 0; j < ZPT2; j++)
            zbase[j * 512] = ZV;
        __threadfence();
        __syncthreads();
        if (tid == 0) atomicAdd(&g_ctr_zero, 1);
        return;
    }

    // ---------------- scan + scatter role ----------------
    __shared__ unsigned long long wlo[16], whi[16];
    __shared__ int count1[G];

    int b = bid, warp = tid >> 5, lane = tid & 31;
    int base = b * N + tid * 4;

    int pk[4]; float gg1[4], gg2[4];
#pragma unroll
    for (int j = 0; j < 4; j++) {
        float4 r = g_rec[base + j];
        pk[j] = __float_as_int(r.x);
        gg1[j] = r.y; gg2[j] = r.z;
    }

    // ---- pass 1: top-1 ----
    unsigned long long lo = 0, hi = 0;
#pragma unroll
    for (int j = 0; j < 4; j++) {
        int i1 = pk[j] & 15;
        if (i1 < 4) lo += 1ULL << (i1 * 16); else hi += 1ULL << ((i1 - 4) * 16);
    }
    unsigned long long slo = lo, shi = hi;
#pragma unroll
    for (int o = 1; o < 32; o <<= 1) {
        unsigned long long t1 = __shfl_up_sync(FULL, slo, o);
        unsigned long long t2 = __shfl_up_sync(FULL, shi, o);
        if (lane >= o) { slo += t1; shi += t2; }
    }
    if (lane == 31) { wlo[warp] = slo; whi[warp] = shi; }
    __syncthreads();
    unsigned long long plo = 0, phi = 0, tlo = 0, thi = 0;
#pragma unroll
    for (int ww = 0; ww < 16; ww++) {
        unsigned long long a = wlo[ww], c = whi[ww];
        if (ww < warp) { plo += a; phi += c; }
        tlo += a; thi += c;
    }
    unsigned long long exlo = plo + slo - lo;
    unsigned long long exhi = phi + shi - hi;
#pragma unroll
    for (int e = 0; e < 4; e++) {
        count1[e]     = min((int)((tlo >> (e * 16)) & 0xFFFF), CAP);
        count1[e + 4] = min((int)((thi >> (e * 16)) & 0xFFFF), CAP);
    }
    int pos1[4];
    {
        unsigned long long rlo = exlo, rhi = exhi;
#pragma unroll
        for (int j = 0; j < 4; j++) {
            int i1 = pk[j] & 15;
            pos1[j] = (i1 < 4) ? (int)((rlo >> (i1 * 16)) & 0xFFFF)
                               : (int)((rhi >> ((i1 - 4) * 16)) & 0xFFFF);
            if (i1 < 4) rlo += 1ULL << (i1 * 16); else rhi += 1ULL << ((i1 - 4) * 16);
        }
    }
    __syncthreads();   // wlo/whi reuse

    // ---- pass 2: top-2 ----
    lo = 0; hi = 0;
#pragma unroll
    for (int j = 0; j < 4; j++) {
        if (pk[j] >> 8) {
            int i2 = (pk[j] >> 4) & 15;
            if (i2 < 4) lo += 1ULL << (i2 * 16); else hi += 1ULL << ((i2 - 4) * 16);
        }
    }
    slo = lo; shi = hi;
#pragma unroll
    for (int o = 1; o < 32; o <<= 1) {
        unsigned long long t1 = __shfl_up_sync(FULL, slo, o);
        unsigned long long t2 = __shfl_up_sync(FULL, shi, o);
        if (lane >= o) { slo += t1; shi += t2; }
    }
    if (lane == 31) { wlo[warp] = slo; whi[warp] = shi; }
    __syncthreads();
    plo = 0; phi = 0;
#pragma unroll
    for (int ww = 0; ww < 16; ww++) {
        if (ww < warp) { plo += wlo[ww]; phi += whi[ww]; }
    }
    exlo = plo + slo - lo;
    exhi = phi + shi - hi;

    // Final scatter targets into registers
    int soff1[4], soff2[4];
    {
        unsigned long long rlo = exlo, rhi = exhi;
#pragma unroll
        for (int j = 0; j < 4; j++) {
            int i1 = pk[j] & 15, i2 = (pk[j] >> 4) & 15, use2 = pk[j] >> 8;
            soff1[j] = (pos1[j] < CAP) ? i1 * CAP + pos1[j] : -1;
            soff2[j] = -1;
            if (use2) {
                int p = (i2 < 4) ? (int)((rlo >> (i2 * 16)) & 0xFFFF)
                                 : (int)((rhi >> ((i2 - 4) * 16)) & 0xFFFF);
                int pos2 = count1[i2] + p;
                if (pos2 < CAP) soff2[j] = i2 * CAP + pos2;
                if (i2 < 4) rlo += 1ULL << (i2 * 16); else rhi += 1ULL << ((i2 - 4) * 16);
            }
        }
    }

    // Batches 3..7 live in the K2-zeroed region: wait for all zero chunks.
    if (b >= 3) {
        if (tid == 0) {
            while (atomicAdd(&g_ctr_zero, 0) < NZ2) __nanosleep(128);
        }
        __syncthreads();
        __threadfence();   // acquire
    }

    // Scatter (<=2 floats per token)
#pragma unroll
    for (int j = 0; j < 4; j++) {
        int t = base + j;
        float* o = out + (size_t)t * SLAB;
        if (soff1[j] >= 0) o[soff1[j]] = gg1[j];
        if (soff2[j] >= 0) o[soff2[j]] = gg2[j];
    }

    // Counter reset for graph replay: last scan block resets both counters.
    // Safe: done-count hits 8 only after batches>=3 passed the zero-wait,
    // which happens only after all 640 zero increments.
    __syncthreads();
    if (tid == 0) {
        int v = atomicAdd(&g_ctr_done, 1);
        if (v == 7) {
            g_ctr_zero = 0;
            g_ctr_done = 0;
            __threadfence();
        }
    }
}

extern "C" void kernel_launch(void* const* d_in, const int* in_sizes, int n_in,
                              void* d_out, int out_size) {
    const float* x = (const float*)d_in[0];
    const float* w = (const float*)d_in[1];
    float* out = (float*)d_out;

    k_gz<<<896, 256>>>(x, w, out);
    k_zs<<<8 + NZ2, 512>>>(out);
}